// round 1
// baseline (speedup 1.0000x reference)
#include <cuda_runtime.h>
#include <cuda_bf16.h>
#include <cstdint>

// BitLevelMapper: B=4194304 rows x 16 bits.
// bits:   [B,16] int32 {0,1}  (d_in[0])
// tables: [16, 32768] float32 {0,1} (d_in[1])
// out:    [B,16] float32
//
// Strategy: row i of the table only uses addresses < 2^i and holds {0,1}
// values, so the whole useful table packs into 2052 uint32 words (8.2KB).
// Kernel 1 packs it into a __device__ global; kernel 2 stages it in shared
// and does the whole mapping with 1 LDS + shift per output bit.

#define NBITS   16
#define TSIZE   32768           // 2^15 entries per table row
#define NWORDS  2052            // sum over i of ceil(max(2^i,32)/32)

__device__ uint32_t g_packed[NWORDS];

// Compact layout offsets (in 32-bit words) for each table row i.
// rows 0..5: 1 word each; row i>=6: 2^(i-5) words.
__device__ __constant__ int c_off[17] =
    {0,1,2,3,4,5,6,8,12,20,36,68,132,260,516,1028,2052};

__global__ void pack_tables_kernel(const float* __restrict__ tables) {
    int w = blockIdx.x * blockDim.x + threadIdx.x;
    if (w >= NWORDS) return;
    // find which table row this word belongs to
    int i = 0;
    #pragma unroll
    for (int r = 1; r < 16; r++)
        if (w >= c_off[r]) i = r;
    int lw = w - c_off[i];
    uint32_t word = 0;
    const float* row = tables + (size_t)i * TSIZE;
    #pragma unroll 8
    for (int b = 0; b < 32; b++) {
        int addr = lw * 32 + b;          // always < TSIZE
        if (row[addr] != 0.0f) word |= (1u << b);
    }
    g_packed[w] = word;
}

__global__ void __launch_bounds__(256)
map_kernel(const int4* __restrict__ bits4, float4* __restrict__ out4, int nrows) {
    __shared__ uint32_t s_tab[NWORDS];
    for (int t = threadIdx.x; t < NWORDS; t += blockDim.x)
        s_tab[t] = g_packed[t];
    __syncthreads();

    int row = blockIdx.x * blockDim.x + threadIdx.x;
    if (row >= nrows) return;

    // Load 16 input bits (64B) as 4 x int4
    int4 v0 = bits4[(size_t)row * 4 + 0];
    int4 v1 = bits4[(size_t)row * 4 + 1];
    int4 v2 = bits4[(size_t)row * 4 + 2];
    int4 v3 = bits4[(size_t)row * 4 + 3];
    int b[16] = { v0.x, v0.y, v0.z, v0.w,
                  v1.x, v1.y, v1.z, v1.w,
                  v2.x, v2.y, v2.z, v2.w,
                  v3.x, v3.y, v3.z, v3.w };

    // bits_rev[k] = b[15-k]; full 15-bit context address
    unsigned A = 0;
    #pragma unroll
    for (int k = 0; k < 15; k++)
        A |= ((unsigned)b[15 - k] & 1u) << k;

    float o[16];
    #pragma unroll
    for (int i = 0; i < 16; i++) {
        unsigned addr = A & ((1u << i) - 1u);      // prefix of A
        uint32_t wv = s_tab[c_off[i] + (addr >> 5)];
        int flip = (int)((wv >> (addr & 31u)) & 1u);
        int bi = b[15 - i] & 1;
        o[15 - i] = (float)(bi ^ flip);            // un-reverse on store
    }

    size_t ob = (size_t)row * 4;
    out4[ob + 0] = make_float4(o[0],  o[1],  o[2],  o[3]);
    out4[ob + 1] = make_float4(o[4],  o[5],  o[6],  o[7]);
    out4[ob + 2] = make_float4(o[8],  o[9],  o[10], o[11]);
    out4[ob + 3] = make_float4(o[12], o[13], o[14], o[15]);
}

extern "C" void kernel_launch(void* const* d_in, const int* in_sizes, int n_in,
                              void* d_out, int out_size) {
    const int4*  bits4  = (const int4*)d_in[0];
    const float* tables = (const float*)d_in[1];
    float4*      out4   = (float4*)d_out;

    int nrows = in_sizes[0] / NBITS;   // 4194304

    pack_tables_kernel<<<(NWORDS + 255) / 256, 256>>>(tables);
    map_kernel<<<(nrows + 255) / 256, 256>>>(bits4, out4, nrows);
}

// round 2
// speedup vs baseline: 1.1711x; 1.1711x over previous
#include <cuda_runtime.h>
#include <cuda_bf16.h>
#include <cstdint>

// BitLevelMapper: B=4194304 rows x 16 bits.
// bits:   [B,16] int32 {0,1}  (d_in[0])
// tables: [16, 32768] float32 {0,1} (d_in[1])
// out:    [B,16] float32
//
// R2: coalesced quad-per-thread layout. 4 lanes cooperate on one row via
// shfl_xor OR-reduction of the 16-bit pattern; every LDG.128/STG.128 is
// fully sector-packed (was 50% packed at 64B stride). Grid-stride 2048
// blocks cuts table staging L2 traffic 134MB -> 17MB.

#define NBITS   16
#define TSIZE   32768           // 2^15 entries per table row
#define NWORDS  2052            // sum over i of ceil(max(2^i,32)/32)

__device__ uint32_t g_packed[NWORDS];

// word offset of table row i in the packed layout
__host__ __device__ __forceinline__ int tab_off(int i) {
    return (i < 5) ? i : ((1 << (i - 5)) + 4);
}

__global__ void pack_tables_kernel(const float* __restrict__ tables) {
    int w = blockIdx.x * blockDim.x + threadIdx.x;
    if (w >= NWORDS) return;
    int i = 0;
    #pragma unroll
    for (int r = 1; r < 16; r++)
        if (w >= tab_off(r)) i = r;
    int lw = w - tab_off(i);
    uint32_t word = 0;
    const float* row = tables + (size_t)i * TSIZE;
    #pragma unroll 8
    for (int b = 0; b < 32; b++) {
        int addr = lw * 32 + b;          // always < TSIZE
        if (row[addr] != 0.0f) word |= (1u << b);
    }
    g_packed[w] = word;
}

#define MAP_BLOCKS  2048
#define MAP_THREADS 256

__global__ void __launch_bounds__(MAP_THREADS)
map_kernel(const int4* __restrict__ bits4, float4* __restrict__ out4, int nquads) {
    __shared__ uint32_t s_tab[NWORDS];
    for (int t = threadIdx.x; t < NWORDS; t += blockDim.x)
        s_tab[t] = g_packed[t];
    __syncthreads();

    const int stride = gridDim.x * blockDim.x;
    const int base   = blockIdx.x * blockDim.x + threadIdx.x;
    const int q      = base & 3;           // quarter within row (lane-group pos)
    const int shift  = 15 - 4 * q;         // bit position of v.x in pattern P

    const int nmain = nquads / stride;     // full iterations (no tail divergence)

    for (int it = 0; it < nmain; it++) {
        int t = base + it * stride;
        int4 v = bits4[t];

        // partial 16-bit pattern: bit j (array order) sits at position 15-j
        unsigned P = ((unsigned)v.x << shift)       | ((unsigned)v.y << (shift - 1))
                   | ((unsigned)v.z << (shift - 2)) | ((unsigned)v.w << (shift - 3));
        // OR-reduce across the aligned 4-lane group -> full pattern in all 4 lanes
        P |= __shfl_xor_sync(0xffffffffu, P, 1);
        P |= __shfl_xor_sync(0xffffffffu, P, 2);

        float o[4];
        #pragma unroll
        for (int m = 0; m < 4; m++) {
            int j = 4 * q + m;
            int i = 15 - j;
            unsigned addr = P & ((1u << i) - 1u);          // prefix of context
            uint32_t wv = s_tab[tab_off(i) + (addr >> 5)];
            int flip = (int)((wv >> (addr & 31u)) & 1u);
            int bi   = (int)((P >> i) & 1u);               // input bit j
            o[m] = (float)(bi ^ flip);
        }
        out4[t] = make_float4(o[0], o[1], o[2], o[3]);
    }

    // tail (not taken for B=4194304, kept for safety; no shuffles here)
    for (int t = base + nmain * stride; t < nquads; t += stride) {
        int row = t >> 2, qq = t & 3;
        const int4* rp = bits4 + (size_t)row * 4;
        int4 r0 = rp[0], r1 = rp[1], r2 = rp[2], r3 = rp[3];
        int b[16] = { r0.x, r0.y, r0.z, r0.w, r1.x, r1.y, r1.z, r1.w,
                      r2.x, r2.y, r2.z, r2.w, r3.x, r3.y, r3.z, r3.w };
        unsigned P = 0;
        #pragma unroll
        for (int j = 0; j < 16; j++) P |= ((unsigned)b[j] & 1u) << (15 - j);
        float o[4];
        #pragma unroll
        for (int m = 0; m < 4; m++) {
            int j = 4 * qq + m;
            int i = 15 - j;
            unsigned addr = P & ((1u << i) - 1u);
            uint32_t wv = s_tab[tab_off(i) + (addr >> 5)];
            int flip = (int)((wv >> (addr & 31u)) & 1u);
            o[m] = (float)(((P >> i) & 1u) ^ (unsigned)flip);
        }
        out4[t] = make_float4(o[0], o[1], o[2], o[3]);
    }
}

extern "C" void kernel_launch(void* const* d_in, const int* in_sizes, int n_in,
                              void* d_out, int out_size) {
    const int4*  bits4  = (const int4*)d_in[0];
    const float* tables = (const float*)d_in[1];
    float4*      out4   = (float4*)d_out;

    int nquads = in_sizes[0] / 4;      // 16777216

    pack_tables_kernel<<<(NWORDS + 255) / 256, 256>>>(tables);
    map_kernel<<<MAP_BLOCKS, MAP_THREADS>>>(bits4, out4, nquads);
}